// round 7
// baseline (speedup 1.0000x reference)
#include <cuda_runtime.h>
#include <cuda_bf16.h>
#include <math.h>
#include <stdint.h>

#define N_NODES 2048
#define BATCH   32
#define HIDDEN  64
#define C_IN    66                 // DIM_IN + HIDDEN
#define BC      2112               // BATCH * C_IN
#define NPAD    2176               // BC padded to multiple of 128
#define IN3     198                // 3 * C_IN
#define GATE_OUT 128
#define UPD_OUT  64

// ---------------- device scratch (static: no allocations allowed) ----------
__device__ __nv_bfloat16 g_Ahi[N_NODES * N_NODES];
__device__ __nv_bfloat16 g_Alo[N_NODES * N_NODES];
__device__ __nv_bfloat16 g_X0Thi[NPAD * N_NODES];
__device__ __nv_bfloat16 g_X0Tlo[NPAD * N_NODES];
__device__ __nv_bfloat16 g_X1Thi[NPAD * N_NODES];
__device__ __nv_bfloat16 g_X1Tlo[NPAD * N_NODES];
__device__ __nv_bfloat16 g_C0Thi[NPAD * N_NODES];
__device__ __nv_bfloat16 g_C0Tlo[NPAD * N_NODES];
__device__ __nv_bfloat16 g_C1Thi[NPAD * N_NODES];
__device__ __nv_bfloat16 g_C1Tlo[NPAD * N_NODES];
__device__ float g_X0[N_NODES * BC];
__device__ float g_X1[N_NODES * BC];
__device__ float g_X2[N_NODES * BC];
__device__ float g_C0[N_NODES * BC];
__device__ float g_C1[N_NODES * BC];
__device__ float g_C2[N_NODES * BC];
__device__ float g_r [BATCH * N_NODES * HIDDEN];

__device__ __forceinline__ uint32_t smem_to_u32(const void* p) {
    uint32_t a;
    asm("{ .reg .u64 t; cvta.to.shared.u64 t, %1; cvt.u32.u64 %0, t; }" : "=r"(a) : "l"(p));
    return a;
}
__device__ __forceinline__ void split_bf16(float v, __nv_bfloat16& hi, __nv_bfloat16& lo) {
    hi = __float2bfloat16(v);
    lo = __float2bfloat16(v - __bfloat162float(hi));
}
__device__ __forceinline__ void mma_bf16(float* c, const uint32_t* a, const uint32_t* b) {
    asm volatile(
        "mma.sync.aligned.m16n8k16.row.col.f32.bf16.bf16.f32 "
        "{%0,%1,%2,%3}, {%4,%5,%6,%7}, {%8,%9}, {%0,%1,%2,%3};"
        : "+f"(c[0]), "+f"(c[1]), "+f"(c[2]), "+f"(c[3])
        : "r"(a[0]), "r"(a[1]), "r"(a[2]), "r"(a[3]), "r"(b[0]), "r"(b[1]));
}
__device__ __forceinline__ void ldsm4(uint32_t* r, uint32_t addr) {
    asm volatile("ldmatrix.sync.aligned.m8n8.x4.shared.b16 {%0,%1,%2,%3}, [%4];"
                 : "=r"(r[0]), "=r"(r[1]), "=r"(r[2]), "=r"(r[3]) : "r"(addr));
}
__device__ __forceinline__ void cp16(uint32_t daddr, const void* g) {
    asm volatile("cp.async.cg.shared.global [%0], [%1], 16;" :: "r"(daddr), "l"(g));
}
__device__ __forceinline__ unsigned long long pack_dup(float b) {
    unsigned long long r;
    asm("mov.b64 %0, {%1, %1};" : "=l"(r) : "f"(b));
    return r;
}
__device__ __forceinline__ void ffma2(unsigned long long& d,
                                      unsigned long long a,
                                      unsigned long long b) {
    asm("fma.rn.f32x2 %0, %1, %2, %0;" : "+l"(d) : "l"(a), "l"(b));
}

// ---------------- K1: supports = softmax(relu(E E^T)) -> bf16 hi/lo --------
__global__ void supports_kernel(const float* __restrict__ E) {
    int n = blockIdx.x;
    int t = threadIdx.x;                      // 256 threads, 8 cols each
    float e[10];
#pragma unroll
    for (int c = 0; c < 10; c++) e[c] = E[n * 10 + c];

    float vals[8];
    float vmax = 0.0f;
#pragma unroll
    for (int j = 0; j < 8; j++) {
        int m = j * 256 + t;
        float s = 0.0f;
#pragma unroll
        for (int c = 0; c < 10; c++) s = fmaf(e[c], E[m * 10 + c], s);
        s = fmaxf(s, 0.0f);
        vals[j] = s;
        vmax = fmaxf(vmax, s);
    }
    __shared__ float red[256];
    red[t] = vmax; __syncthreads();
    for (int s = 128; s > 0; s >>= 1) {
        if (t < s) red[t] = fmaxf(red[t], red[t + s]);
        __syncthreads();
    }
    vmax = red[0]; __syncthreads();

    float lsum = 0.0f;
#pragma unroll
    for (int j = 0; j < 8; j++) { vals[j] = expf(vals[j] - vmax); lsum += vals[j]; }
    red[t] = lsum; __syncthreads();
    for (int s = 128; s > 0; s >>= 1) {
        if (t < s) red[t] += red[t + s];
        __syncthreads();
    }
    float inv = 1.0f / red[0];
#pragma unroll
    for (int j = 0; j < 8; j++) {
        float v = vals[j] * inv;
        __nv_bfloat16 hi, lo;
        split_bf16(v, hi, lo);
        g_Ahi[(size_t)n * N_NODES + j * 256 + t] = hi;
        g_Alo[(size_t)n * N_NODES + j * 256 + t] = lo;
    }
}

// ---------------- K2: pack X0 (fp32 [node][bc]) + X0T hi/lo ([bc][node]) ---
__global__ void pack_kernel(const float* __restrict__ x, const float* __restrict__ st) {
    int n = blockIdx.x;
    for (int i = threadIdx.x; i < BC; i += blockDim.x) {
        int b = i / C_IN, c = i - b * C_IN;
        float v = (c < 2) ? x[(b * N_NODES + n) * 2 + c]
                          : st[(b * N_NODES + n) * 64 + (c - 2)];
        g_X0[n * BC + i] = v;
        __nv_bfloat16 hi, lo;
        split_bf16(v, hi, lo);
        g_X0Thi[(size_t)i * N_NODES + n] = hi;
        g_X0Tlo[(size_t)i * N_NODES + n] = lo;
    }
}

// ---------------- K2b: zero pad rows [BC..NPAD) of transposed arrays -------
__global__ void pad_kernel() {
    int idx = blockIdx.x * 256 + threadIdx.x;   // (NPAD-BC)*2048 = 131072
    if (idx < (NPAD - BC) * N_NODES) {
        size_t off = (size_t)BC * N_NODES + idx;
        g_X0Thi[off] = __float2bfloat16(0.f);
        g_X0Tlo[off] = __float2bfloat16(0.f);
        g_C0Thi[off] = __float2bfloat16(0.f);
        g_C0Tlo[off] = __float2bfloat16(0.f);
    }
}

// ---------------- HMMA GEMM: D[m,n] = sum_k A[m,k] * BT[n,k] ---------------
// bf16 3-split (AhiBhi + AhiBlo + AloBhi), fp32 acc.
// CTA tile 256x128, 16 warps of 32x64 (512 threads), BK=32, double buffer.
// smem per buffer (73728B): Ahi@0 (2 slices x 12288), Alo@24576,
//                           Bhi@49152 (2 x 6144), Blo@61440.
// Row stride 48B (16 bf16 data + 16B pad) -> conflict-free ldmatrix.
template <int MODE>
__global__ void __launch_bounds__(512, 1)
mma_gemm(const __nv_bfloat16* __restrict__ Ahi, const __nv_bfloat16* __restrict__ Alo,
         const __nv_bfloat16* __restrict__ Bhi, const __nv_bfloat16* __restrict__ Blo,
         float* __restrict__ Cf, __nv_bfloat16* __restrict__ CThi,
         __nv_bfloat16* __restrict__ CTlo, const float* __restrict__ Aux) {
    extern __shared__ char smem[];
    const uint32_t sb = smem_to_u32(smem);
    const int tid = threadIdx.x, wid = tid >> 5, lane = tid & 31;
    const int wr = wid >> 1, wc = wid & 1;            // warp tile: 32x64
    const int m0 = blockIdx.y * 256, n0 = blockIdx.x * 128;

    const __nv_bfloat16* srcA[2] = { Ahi + (size_t)m0 * N_NODES,
                                     Alo + (size_t)m0 * N_NODES };
    const __nv_bfloat16* srcB[2] = { Bhi + (size_t)n0 * N_NODES,
                                     Blo + (size_t)n0 * N_NODES };

    float acc[2][8][4];
#pragma unroll
    for (int i = 0; i < 2; i++)
#pragma unroll
        for (int j = 0; j < 8; j++)
#pragma unroll
            for (int k = 0; k < 4; k++) acc[i][j][k] = 0.f;

#define COPY_CHUNK(k0, bufi) do {                                             \
        uint32_t _b = sb + (bufi) * 73728;                                    \
        _Pragma("unroll")                                                     \
        for (int _t = 0; _t < 2; _t++) {          /* A hi/lo: 2 units */      \
            _Pragma("unroll")                                                 \
            for (int _u = 0; _u < 2; _u++) {                                  \
                int _unit = _u * 512 + tid;                                   \
                int _row = _unit >> 2, _q = _unit & 3;                        \
                int _sl = _q >> 1, _hf = _q & 1;                              \
                cp16(_b + _t * 24576 + _sl * 12288 + _row * 48 + _hf * 16,    \
                     srcA[_t] + (size_t)_row * N_NODES + (k0) + _sl * 16 + _hf * 8); \
            }                                                                 \
        }                                                                     \
        _Pragma("unroll")                                                     \
        for (int _t = 0; _t < 2; _t++) {          /* B hi/lo: 1 unit */       \
            int _row = tid >> 2, _q = tid & 3;                                \
            int _sl = _q >> 1, _hf = _q & 1;                                  \
            cp16(_b + 49152 + _t * 12288 + _sl * 6144 + _row * 48 + _hf * 16, \
                 srcB[_t] + (size_t)_row * N_NODES + (k0) + _sl * 16 + _hf * 8); \
        }                                                                     \
        asm volatile("cp.async.commit_group;");                               \
    } while (0)

    COPY_CHUNK(0, 0);

    const int NCHUNK = N_NODES / 32;   // 64
    for (int c = 0; c < NCHUNK; c++) {
        int buf = c & 1;
        if (c + 1 < NCHUNK) {
            COPY_CHUNK((c + 1) * 32, buf ^ 1);
            asm volatile("cp.async.wait_group 1;");
        } else {
            asm volatile("cp.async.wait_group 0;");
        }
        __syncthreads();

        uint32_t base = sb + buf * 73728;

#pragma unroll
        for (int s = 0; s < 2; s++) {
            uint32_t a_hi[2][4], a_lo[2][4];
            int a_roff = (wr * 32 + (lane & 15)) * 48 + (lane >> 4) * 16 + s * 12288;
#pragma unroll
            for (int mt = 0; mt < 2; mt++) {
                ldsm4(a_hi[mt], base + a_roff + mt * 768);
                ldsm4(a_lo[mt], base + 24576 + a_roff + mt * 768);
            }
            int q = lane >> 3, rl = lane & 7;
            int b_roff = (wc * 64 + (q >> 1) * 8 + rl) * 48 + (q & 1) * 16 + s * 6144;
#pragma unroll
            for (int p = 0; p < 4; p++) {           // 16-col groups
                uint32_t b_hi[4], b_lo[4];
                ldsm4(b_hi, base + 49152 + b_roff + p * 768);
                ldsm4(b_lo, base + 61440 + b_roff + p * 768);
#pragma unroll
                for (int mt = 0; mt < 2; mt++) {
#pragma unroll
                    for (int h = 0; h < 2; h++) {
                        int nt = p * 2 + h;
                        mma_bf16(acc[mt][nt], a_hi[mt], &b_hi[h * 2]);
                        mma_bf16(acc[mt][nt], a_hi[mt], &b_lo[h * 2]);
                        mma_bf16(acc[mt][nt], a_lo[mt], &b_hi[h * 2]);
                    }
                }
            }
        }
        __syncthreads();
    }
#undef COPY_CHUNK

    // ---- epilogue: fp32 row-major direct from fragments ----
    const int frow = lane >> 2, fcol = (lane & 3) * 2;
#pragma unroll
    for (int mt = 0; mt < 2; mt++) {
#pragma unroll
        for (int nt = 0; nt < 8; nt++) {
            int m = m0 + wr * 32 + mt * 16 + frow;
            int n = n0 + wc * 64 + nt * 8 + fcol;
            if (n < BC) {
                float* d0 = Cf + (size_t)m * BC + n;
                float* d1 = Cf + (size_t)(m + 8) * BC + n;
                if (MODE == 1) {
                    float2 x0 = *(const float2*)(Aux + (size_t)m * BC + n);
                    float2 x1 = *(const float2*)(Aux + (size_t)(m + 8) * BC + n);
                    *(float2*)d0 = make_float2(2.f * acc[mt][nt][0] - x0.x,
                                               2.f * acc[mt][nt][1] - x0.y);
                    *(float2*)d1 = make_float2(2.f * acc[mt][nt][2] - x1.x,
                                               2.f * acc[mt][nt][3] - x1.y);
                } else {
                    *(float2*)d0 = make_float2(acc[mt][nt][0], acc[mt][nt][1]);
                    *(float2*)d1 = make_float2(acc[mt][nt][2], acc[mt][nt][3]);
                }
            }
        }
    }

    if (MODE == 0) {
        // ---- transpose via smem -> bf16 hi/lo [n][node] ----
        float* Ct = (float*)smem;          // [128 n][264 m] fp32 = 135168B
        __syncthreads();
#pragma unroll
        for (int mt = 0; mt < 2; mt++) {
#pragma unroll
            for (int nt = 0; nt < 8; nt++) {
                int mloc = wr * 32 + mt * 16 + frow;
                int nloc = wc * 64 + nt * 8 + fcol;
                Ct[(nloc + 0) * 264 + mloc]     = acc[mt][nt][0];
                Ct[(nloc + 1) * 264 + mloc]     = acc[mt][nt][1];
                Ct[(nloc + 0) * 264 + mloc + 8] = acc[mt][nt][2];
                Ct[(nloc + 1) * 264 + mloc + 8] = acc[mt][nt][3];
            }
        }
        __syncthreads();
        for (int it = 0; it < 8; it++) {
            int nloc = it * 16 + wid;
#pragma unroll
            for (int j = 0; j < 2; j++) {
                int mloc = lane * 4 + j * 128;
                float4 v = *(float4*)&Ct[nloc * 264 + mloc];
                __nv_bfloat16 hi[4], lo[4];
                split_bf16(v.x, hi[0], lo[0]);
                split_bf16(v.y, hi[1], lo[1]);
                split_bf16(v.z, hi[2], lo[2]);
                split_bf16(v.w, hi[3], lo[3]);
                size_t off = (size_t)(n0 + nloc) * N_NODES + m0 + mloc;
                *(uint2*)(CThi + off) = *(uint2*)hi;
                *(uint2*)(CTlo + off) = *(uint2*)lo;
            }
        }
    }
}

// ---------------- K4: gate projection + sigmoid + candidate pack -----------
// in_s transposed: [i][16 rows] so row pairs are contiguous for LDS.64+FFMA2.
__global__ void __launch_bounds__(128)
gate_kernel(const float* __restrict__ x, const float* __restrict__ st,
            const float* __restrict__ Wg, const float* __restrict__ bg) {
    __shared__ float in_s[IN3][16];
    int row0 = blockIdx.x * 16;
    int t = threadIdx.x;

    for (int idx = t; idx < 16 * IN3; idx += 128) {
        int i = idx >> 4, rr = idx & 15;
        int row = row0 + rr;
        int b = row >> 11, n = row & 2047;
        int k = i / C_IN, c = i - k * C_IN;
        const float* src = (k == 0) ? g_X0 : (k == 1) ? g_X1 : g_X2;
        in_s[i][rr] = src[n * BC + b * C_IN + c];
    }
    __syncthreads();

    int o = t;
    unsigned long long acc2[8];
#pragma unroll
    for (int pp = 0; pp < 8; pp++) acc2[pp] = 0ULL;
    for (int i = 0; i < IN3; i++) {
        unsigned long long wd = pack_dup(Wg[i * GATE_OUT + o]);
#pragma unroll
        for (int pp = 0; pp < 8; pp++)
            ffma2(acc2[pp], *(const unsigned long long*)&in_s[i][pp * 2], wd);
    }
    float bias = bg[o];
#pragma unroll
    for (int pp = 0; pp < 8; pp++) {
        float2 f = *(float2*)&acc2[pp];
#pragma unroll
        for (int h = 0; h < 2; h++) {
            int row = row0 + pp * 2 + h;
            int b = row >> 11, n = row & 2047;
            float v = 1.0f / (1.0f + expf(-((h ? f.y : f.x) + bias)));
            if (o < 64) {
                float sv = st[row * 64 + o];
                float cv = v * sv;                                  // z * state
                g_C0[n * BC + b * C_IN + 2 + o] = cv;
                __nv_bfloat16 hi, lo;
                split_bf16(cv, hi, lo);
                g_C0Thi[(size_t)(b * C_IN + 2 + o) * N_NODES + n] = hi;
                g_C0Tlo[(size_t)(b * C_IN + 2 + o) * N_NODES + n] = lo;
                if (o < 2) {
                    float xv = x[row * 2 + o];
                    g_C0[n * BC + b * C_IN + o] = xv;
                    split_bf16(xv, hi, lo);
                    g_C0Thi[(size_t)(b * C_IN + o) * N_NODES + n] = hi;
                    g_C0Tlo[(size_t)(b * C_IN + o) * N_NODES + n] = lo;
                }
            } else {
                g_r[row * 64 + (o - 64)] = v;                        // r gate
            }
        }
    }
}

// ---------------- K5: update projection + tanh + GRU blend -----------------
__global__ void __launch_bounds__(128)
update_kernel(const float* __restrict__ st, const float* __restrict__ Wu,
              const float* __restrict__ bu, float* __restrict__ out) {
    __shared__ float in_s[IN3][16];
    int row0 = blockIdx.x * 16;
    int t = threadIdx.x;

    for (int idx = t; idx < 16 * IN3; idx += 128) {
        int i = idx >> 4, rr = idx & 15;
        int row = row0 + rr;
        int b = row >> 11, n = row & 2047;
        int k = i / C_IN, c = i - k * C_IN;
        const float* src = (k == 0) ? g_C0 : (k == 1) ? g_C1 : g_C2;
        in_s[i][rr] = src[n * BC + b * C_IN + c];
    }
    __syncthreads();

    int o = t & 63, hh = t >> 6;
    unsigned long long acc2[4];
#pragma unroll
    for (int pp = 0; pp < 4; pp++) acc2[pp] = 0ULL;
    for (int i = 0; i < IN3; i++) {
        unsigned long long wd = pack_dup(Wu[i * UPD_OUT + o]);
#pragma unroll
        for (int pp = 0; pp < 4; pp++)
            ffma2(acc2[pp], *(const unsigned long long*)&in_s[i][hh * 8 + pp * 2], wd);
    }
    float bias = bu[o];
#pragma unroll
    for (int pp = 0; pp < 4; pp++) {
        float2 f = *(float2*)&acc2[pp];
#pragma unroll
        for (int h = 0; h < 2; h++) {
            int row = row0 + hh * 8 + pp * 2 + h;
            float hc = tanhf((h ? f.y : f.x) + bias);
            float rv = g_r[row * 64 + o];
            float sv = st[row * 64 + o];
            out[row * 64 + o] = rv * sv + (1.0f - rv) * hc;
        }
    }
}

// ---------------- launch ----------------------------------------------------
extern "C" void kernel_launch(void* const* d_in, const int* in_sizes, int n_in,
                              void* d_out, int out_size) {
    const float* x  = (const float*)d_in[0];
    const float* st = (const float*)d_in[1];
    const float* E  = (const float*)d_in[2];
    const float* Wg = (const float*)d_in[3];
    const float* bg = (const float*)d_in[4];
    const float* Wu = (const float*)d_in[5];
    const float* bu = (const float*)d_in[6];
    float* out = (float*)d_out;

    __nv_bfloat16 *pAhi, *pAlo, *pX0Thi, *pX0Tlo, *pX1Thi, *pX1Tlo;
    __nv_bfloat16 *pC0Thi, *pC0Tlo, *pC1Thi, *pC1Tlo;
    float *pX0, *pX1, *pX2, *pC0, *pC1, *pC2;
    cudaGetSymbolAddress((void**)&pAhi,   g_Ahi);
    cudaGetSymbolAddress((void**)&pAlo,   g_Alo);
    cudaGetSymbolAddress((void**)&pX0Thi, g_X0Thi);
    cudaGetSymbolAddress((void**)&pX0Tlo, g_X0Tlo);
    cudaGetSymbolAddress((void**)&pX1Thi, g_X1Thi);
    cudaGetSymbolAddress((void**)&pX1Tlo, g_X1Tlo);
    cudaGetSymbolAddress((void**)&pC0Thi, g_C0Thi);
    cudaGetSymbolAddress((void**)&pC0Tlo, g_C0Tlo);
    cudaGetSymbolAddress((void**)&pC1Thi, g_C1Thi);
    cudaGetSymbolAddress((void**)&pC1Tlo, g_C1Tlo);
    cudaGetSymbolAddress((void**)&pX0, g_X0);
    cudaGetSymbolAddress((void**)&pX1, g_X1);
    cudaGetSymbolAddress((void**)&pX2, g_X2);
    cudaGetSymbolAddress((void**)&pC0, g_C0);
    cudaGetSymbolAddress((void**)&pC1, g_C1);
    cudaGetSymbolAddress((void**)&pC2, g_C2);

    const int SMEM_BYTES = 2 * 73728;   // 147456 (epilogue Ct uses 135168)
    cudaFuncSetAttribute(mma_gemm<0>, cudaFuncAttributeMaxDynamicSharedMemorySize, SMEM_BYTES);
    cudaFuncSetAttribute(mma_gemm<1>, cudaFuncAttributeMaxDynamicSharedMemorySize, SMEM_BYTES);

    dim3 gg(NPAD / 128, N_NODES / 256);   // (17, 8) = 136 CTAs, single wave

    supports_kernel<<<N_NODES, 256>>>(E);
    pack_kernel<<<N_NODES, 256>>>(x, st);
    pad_kernel<<<512, 256>>>();

    // gate gconv: X1 = A X0 ; X2 = 2 A X1 - X0
    mma_gemm<0><<<gg, 512, SMEM_BYTES>>>(pAhi, pAlo, pX0Thi, pX0Tlo,
                                         pX1, pX1Thi, pX1Tlo, nullptr);
    mma_gemm<1><<<gg, 512, SMEM_BYTES>>>(pAhi, pAlo, pX1Thi, pX1Tlo,
                                         pX2, nullptr, nullptr, pX0);

    gate_kernel<<<(BATCH * N_NODES) / 16, 128>>>(x, st, Wg, bg);

    // update gconv: C1 = A C0 ; C2 = 2 A C1 - C0
    mma_gemm<0><<<gg, 512, SMEM_BYTES>>>(pAhi, pAlo, pC0Thi, pC0Tlo,
                                         pC1, pC1Thi, pC1Tlo, nullptr);
    mma_gemm<1><<<gg, 512, SMEM_BYTES>>>(pAhi, pAlo, pC1Thi, pC1Tlo,
                                         pC2, nullptr, nullptr, pC0);

    update_kernel<<<(BATCH * N_NODES) / 16, 128>>>(st, Wu, bu, out);
}

// round 9
// speedup vs baseline: 1.1691x; 1.1691x over previous
#include <cuda_runtime.h>
#include <cuda_bf16.h>
#include <math.h>
#include <stdint.h>

#define N_NODES 2048
#define BATCH   32
#define HIDDEN  64
#define C_IN    66                 // DIM_IN + HIDDEN
#define BC      2112               // BATCH * C_IN
#define NPAD    2176               // BC padded to multiple of 128
#define IN3     198                // 3 * C_IN
#define GATE_OUT 128
#define UPD_OUT  64

// ---------------- device scratch (static: no allocations allowed) ----------
__device__ __nv_bfloat16 g_Ahi[N_NODES * N_NODES];
__device__ __nv_bfloat16 g_Alo[N_NODES * N_NODES];
__device__ __nv_bfloat16 g_X0Thi[NPAD * N_NODES];
__device__ __nv_bfloat16 g_X0Tlo[NPAD * N_NODES];
__device__ __nv_bfloat16 g_X1Thi[NPAD * N_NODES];
__device__ __nv_bfloat16 g_X1Tlo[NPAD * N_NODES];
__device__ __nv_bfloat16 g_C0Thi[NPAD * N_NODES];
__device__ __nv_bfloat16 g_C0Tlo[NPAD * N_NODES];
__device__ __nv_bfloat16 g_C1Thi[NPAD * N_NODES];
__device__ __nv_bfloat16 g_C1Tlo[NPAD * N_NODES];
__device__ float g_X0[N_NODES * BC];
__device__ float g_X1[N_NODES * BC];
__device__ float g_X2[N_NODES * BC];
__device__ float g_C0[N_NODES * BC];
__device__ float g_C1[N_NODES * BC];
__device__ float g_C2[N_NODES * BC];
__device__ float g_r [BATCH * N_NODES * HIDDEN];

__device__ __forceinline__ uint32_t smem_to_u32(const void* p) {
    uint32_t a;
    asm("{ .reg .u64 t; cvta.to.shared.u64 t, %1; cvt.u32.u64 %0, t; }" : "=r"(a) : "l"(p));
    return a;
}
__device__ __forceinline__ void split_bf16(float v, __nv_bfloat16& hi, __nv_bfloat16& lo) {
    hi = __float2bfloat16(v);
    lo = __float2bfloat16(v - __bfloat162float(hi));
}
__device__ __forceinline__ void mma_bf16(float* c, const uint32_t* a, const uint32_t* b) {
    asm volatile(
        "mma.sync.aligned.m16n8k16.row.col.f32.bf16.bf16.f32 "
        "{%0,%1,%2,%3}, {%4,%5,%6,%7}, {%8,%9}, {%0,%1,%2,%3};"
        : "+f"(c[0]), "+f"(c[1]), "+f"(c[2]), "+f"(c[3])
        : "r"(a[0]), "r"(a[1]), "r"(a[2]), "r"(a[3]), "r"(b[0]), "r"(b[1]));
}
__device__ __forceinline__ void ldsm4(uint32_t* r, uint32_t addr) {
    asm volatile("ldmatrix.sync.aligned.m8n8.x4.shared.b16 {%0,%1,%2,%3}, [%4];"
                 : "=r"(r[0]), "=r"(r[1]), "=r"(r[2]), "=r"(r[3]) : "r"(addr));
}
__device__ __forceinline__ void cp16(uint32_t daddr, const void* g) {
    asm volatile("cp.async.cg.shared.global [%0], [%1], 16;" :: "r"(daddr), "l"(g));
}

// ---------------- K1: supports = softmax(relu(E E^T)) -> bf16 hi/lo --------
__global__ void supports_kernel(const float* __restrict__ E) {
    int n = blockIdx.x;
    int t = threadIdx.x;                      // 256 threads, 8 cols each
    float e[10];
#pragma unroll
    for (int c = 0; c < 10; c++) e[c] = E[n * 10 + c];

    float vals[8];
    float vmax = 0.0f;
#pragma unroll
    for (int j = 0; j < 8; j++) {
        int m = j * 256 + t;
        float s = 0.0f;
#pragma unroll
        for (int c = 0; c < 10; c++) s = fmaf(e[c], E[m * 10 + c], s);
        s = fmaxf(s, 0.0f);
        vals[j] = s;
        vmax = fmaxf(vmax, s);
    }
    __shared__ float red[256];
    red[t] = vmax; __syncthreads();
    for (int s = 128; s > 0; s >>= 1) {
        if (t < s) red[t] = fmaxf(red[t], red[t + s]);
        __syncthreads();
    }
    vmax = red[0]; __syncthreads();

    float lsum = 0.0f;
#pragma unroll
    for (int j = 0; j < 8; j++) { vals[j] = expf(vals[j] - vmax); lsum += vals[j]; }
    red[t] = lsum; __syncthreads();
    for (int s = 128; s > 0; s >>= 1) {
        if (t < s) red[t] += red[t + s];
        __syncthreads();
    }
    float inv = 1.0f / red[0];
#pragma unroll
    for (int j = 0; j < 8; j++) {
        float v = vals[j] * inv;
        __nv_bfloat16 hi, lo;
        split_bf16(v, hi, lo);
        g_Ahi[(size_t)n * N_NODES + j * 256 + t] = hi;
        g_Alo[(size_t)n * N_NODES + j * 256 + t] = lo;
    }
}

// ---------------- K2: pack X0 fp32 [node][bc] only (coalesced) -------------
__global__ void pack_kernel(const float* __restrict__ x, const float* __restrict__ st) {
    int n = blockIdx.x;
    for (int i = threadIdx.x; i < BC; i += blockDim.x) {
        int b = i / C_IN, c = i - b * C_IN;
        float v = (c < 2) ? x[(b * N_NODES + n) * 2 + c]
                          : st[(b * N_NODES + n) * 64 + (c - 2)];
        g_X0[n * BC + i] = v;
    }
}

// ---------------- K3: tiled transpose+split: src[N][BC] -> dst[NPAD][N] ----
// 64x64 tiles via smem; all global accesses coalesced. Pad rows -> zeros.
__global__ void __launch_bounds__(256)
transpose_split_kernel(const float* __restrict__ src,
                       __nv_bfloat16* __restrict__ dhi,
                       __nv_bfloat16* __restrict__ dlo) {
    __shared__ float tile[64][65];
    int i0 = blockIdx.x * 64;          // col in src = row in dst
    int n0 = blockIdx.y * 64;
    int t = threadIdx.x;
    int iloc = t >> 2;                 // 0..63
    int seg  = (t & 3) * 16;           // 16 elems per thread

    if (i0 < BC) {
        int nloc = t >> 2;
#pragma unroll
        for (int g = 0; g < 4; g++) {
            float4 v = *(const float4*)(src + (size_t)(n0 + nloc) * BC + i0 + seg + g * 4);
            tile[seg + g * 4 + 0][nloc] = v.x;
            tile[seg + g * 4 + 1][nloc] = v.y;
            tile[seg + g * 4 + 2][nloc] = v.z;
            tile[seg + g * 4 + 3][nloc] = v.w;
        }
        __syncthreads();
        __nv_bfloat16 hi[16], lo[16];
#pragma unroll
        for (int g = 0; g < 16; g++)
            split_bf16(tile[iloc][seg + g], hi[g], lo[g]);
        size_t off = (size_t)(i0 + iloc) * N_NODES + n0 + seg;
        *(uint4*)(dhi + off)     = *(uint4*)&hi[0];
        *(uint4*)(dhi + off + 8) = *(uint4*)&hi[8];
        *(uint4*)(dlo + off)     = *(uint4*)&lo[0];
        *(uint4*)(dlo + off + 8) = *(uint4*)&lo[8];
    } else {                            // pad rows: zeros
        uint4 z = make_uint4(0, 0, 0, 0);
        size_t off = (size_t)(i0 + iloc) * N_NODES + n0 + seg;
        *(uint4*)(dhi + off)     = z;
        *(uint4*)(dhi + off + 8) = z;
        *(uint4*)(dlo + off)     = z;
        *(uint4*)(dlo + off + 8) = z;
    }
}

// ---------------- HMMA GEMM: D[m,n] = sum_k A[m,k] * BT[n,k] ---------------
// bf16 3-split (AhiBhi + AhiBlo + AloBhi), fp32 acc.
// CTA tile 256x128, 8 warps of 64x64, BK=32, cp.async double buffer.
template <int MODE>
__global__ void __launch_bounds__(256, 1)
mma_gemm(const __nv_bfloat16* __restrict__ Ahi, const __nv_bfloat16* __restrict__ Alo,
         const __nv_bfloat16* __restrict__ Bhi, const __nv_bfloat16* __restrict__ Blo,
         float* __restrict__ Cf, __nv_bfloat16* __restrict__ CThi,
         __nv_bfloat16* __restrict__ CTlo, const float* __restrict__ Aux) {
    extern __shared__ char smem[];
    const uint32_t sb = smem_to_u32(smem);
    const int tid = threadIdx.x, wid = tid >> 5, lane = tid & 31;
    const int wr = wid >> 1, wc = wid & 1;            // warp tile: 64x64
    const int m0 = blockIdx.y * 256, n0 = blockIdx.x * 128;

    const __nv_bfloat16* srcA[2] = { Ahi + (size_t)m0 * N_NODES,
                                     Alo + (size_t)m0 * N_NODES };
    const __nv_bfloat16* srcB[2] = { Bhi + (size_t)n0 * N_NODES,
                                     Blo + (size_t)n0 * N_NODES };

    float acc[4][8][4];
#pragma unroll
    for (int i = 0; i < 4; i++)
#pragma unroll
        for (int j = 0; j < 8; j++)
#pragma unroll
            for (int k = 0; k < 4; k++) acc[i][j][k] = 0.f;

#define COPY_CHUNK(k0, bufi) do {                                             \
        uint32_t _b = sb + (bufi) * 73728;                                    \
        _Pragma("unroll")                                                     \
        for (int _t = 0; _t < 2; _t++) {          /* A hi/lo: 4 units */      \
            _Pragma("unroll")                                                 \
            for (int _u = 0; _u < 4; _u++) {                                  \
                int _unit = _u * 256 + tid;                                   \
                int _row = _unit >> 2, _q = _unit & 3;                        \
                int _sl = _q >> 1, _hf = _q & 1;                              \
                cp16(_b + _t * 24576 + _sl * 12288 + _row * 48 + _hf * 16,    \
                     srcA[_t] + (size_t)_row * N_NODES + (k0) + _sl * 16 + _hf * 8); \
            }                                                                 \
        }                                                                     \
        _Pragma("unroll")                                                     \
        for (int _t = 0; _t < 2; _t++) {          /* B hi/lo: 2 units */      \
            _Pragma("unroll")                                                 \
            for (int _u = 0; _u < 2; _u++) {                                  \
                int _unit = _u * 256 + tid;                                   \
                int _row = _unit >> 2, _q = _unit & 3;                        \
                int _sl = _q >> 1, _hf = _q & 1;                              \
                cp16(_b + 49152 + _t * 12288 + _sl * 6144 + _row * 48 + _hf * 16, \
                     srcB[_t] + (size_t)_row * N_NODES + (k0) + _sl * 16 + _hf * 8); \
            }                                                                 \
        }                                                                     \
        asm volatile("cp.async.commit_group;");                               \
    } while (0)

    COPY_CHUNK(0, 0);

    const int NCHUNK = N_NODES / 32;   // 64
    for (int c = 0; c < NCHUNK; c++) {
        int buf = c & 1;
        if (c + 1 < NCHUNK) {
            COPY_CHUNK((c + 1) * 32, buf ^ 1);
            asm volatile("cp.async.wait_group 1;");
        } else {
            asm volatile("cp.async.wait_group 0;");
        }
        __syncthreads();

        uint32_t base = sb + buf * 73728;

#pragma unroll
        for (int s = 0; s < 2; s++) {
            uint32_t a_hi[4][4], a_lo[4][4], b_hi[4][4], b_lo[4][4];
            int a_roff = (wr * 64 + (lane & 15)) * 48 + (lane >> 4) * 16 + s * 12288;
#pragma unroll
            for (int mt = 0; mt < 4; mt++) {
                ldsm4(a_hi[mt], base + a_roff + mt * 768);
                ldsm4(a_lo[mt], base + 24576 + a_roff + mt * 768);
            }
            int q = lane >> 3, rl = lane & 7;
            int b_roff = (wc * 64 + (q >> 1) * 8 + rl) * 48 + (q & 1) * 16 + s * 6144;
#pragma unroll
            for (int p = 0; p < 4; p++) {
                ldsm4(b_hi[p], base + 49152 + b_roff + p * 768);
                ldsm4(b_lo[p], base + 61440 + b_roff + p * 768);
            }
#pragma unroll
            for (int mt = 0; mt < 4; mt++) {
#pragma unroll
                for (int nt = 0; nt < 8; nt++) {
                    const uint32_t* bh = &b_hi[nt >> 1][(nt & 1) * 2];
                    const uint32_t* bl = &b_lo[nt >> 1][(nt & 1) * 2];
                    mma_bf16(acc[mt][nt], a_hi[mt], bh);
                    mma_bf16(acc[mt][nt], a_hi[mt], bl);
                    mma_bf16(acc[mt][nt], a_lo[mt], bh);
                }
            }
        }
        __syncthreads();
    }
#undef COPY_CHUNK

    // ---- epilogue: fp32 row-major direct from fragments ----
    const int frow = lane >> 2, fcol = (lane & 3) * 2;
#pragma unroll
    for (int mt = 0; mt < 4; mt++) {
#pragma unroll
        for (int nt = 0; nt < 8; nt++) {
            int m = m0 + wr * 64 + mt * 16 + frow;
            int n = n0 + wc * 64 + nt * 8 + fcol;
            if (n < BC) {
                float* d0 = Cf + (size_t)m * BC + n;
                float* d1 = Cf + (size_t)(m + 8) * BC + n;
                if (MODE == 1) {
                    float2 x0 = *(const float2*)(Aux + (size_t)m * BC + n);
                    float2 x1 = *(const float2*)(Aux + (size_t)(m + 8) * BC + n);
                    *(float2*)d0 = make_float2(2.f * acc[mt][nt][0] - x0.x,
                                               2.f * acc[mt][nt][1] - x0.y);
                    *(float2*)d1 = make_float2(2.f * acc[mt][nt][2] - x1.x,
                                               2.f * acc[mt][nt][3] - x1.y);
                } else {
                    *(float2*)d0 = make_float2(acc[mt][nt][0], acc[mt][nt][1]);
                    *(float2*)d1 = make_float2(acc[mt][nt][2], acc[mt][nt][3]);
                }
            }
        }
    }

    if (MODE == 0) {
        // ---- transpose via smem -> bf16 hi/lo [n][node] ----
        float* Ct = (float*)smem;          // [128][264] fp32 = 135168B
        __syncthreads();
#pragma unroll
        for (int mt = 0; mt < 4; mt++) {
#pragma unroll
            for (int nt = 0; nt < 8; nt++) {
                int mloc = wr * 64 + mt * 16 + frow;
                int nloc = wc * 64 + nt * 8 + fcol;
                Ct[(nloc + 0) * 264 + mloc]     = acc[mt][nt][0];
                Ct[(nloc + 1) * 264 + mloc]     = acc[mt][nt][1];
                Ct[(nloc + 0) * 264 + mloc + 8] = acc[mt][nt][2];
                Ct[(nloc + 1) * 264 + mloc + 8] = acc[mt][nt][3];
            }
        }
        __syncthreads();
        for (int it = 0; it < 16; it++) {
            int nloc = it * 8 + wid;
#pragma unroll
            for (int j = 0; j < 2; j++) {
                int mloc = lane * 4 + j * 128;
                float4 v = *(float4*)&Ct[nloc * 264 + mloc];
                __nv_bfloat16 hi[4], lo[4];
                split_bf16(v.x, hi[0], lo[0]);
                split_bf16(v.y, hi[1], lo[1]);
                split_bf16(v.z, hi[2], lo[2]);
                split_bf16(v.w, hi[3], lo[3]);
                size_t off = (size_t)(n0 + nloc) * N_NODES + m0 + mloc;
                *(uint2*)(CThi + off) = *(uint2*)hi;
                *(uint2*)(CTlo + off) = *(uint2*)lo;
            }
        }
    }
}

// ---------------- K4: gate projection + sigmoid + candidate pack -----------
__global__ void __launch_bounds__(128)
gate_kernel(const float* __restrict__ x, const float* __restrict__ st,
            const float* __restrict__ Wg, const float* __restrict__ bg) {
    __shared__ float in_s[16][IN3];
    int row0 = blockIdx.x * 16;
    int t = threadIdx.x;

    for (int idx = t; idx < 16 * IN3; idx += 128) {
        int rr = idx / IN3, i = idx - rr * IN3;
        int row = row0 + rr;
        int b = row >> 11, n = row & 2047;
        int k = i / C_IN, c = i - k * C_IN;
        const float* src = (k == 0) ? g_X0 : (k == 1) ? g_X1 : g_X2;
        in_s[rr][i] = src[n * BC + b * C_IN + c];
    }
    __syncthreads();

    int o = t;
    float acc[16];
#pragma unroll
    for (int rr = 0; rr < 16; rr++) acc[rr] = 0.0f;
    for (int i = 0; i < IN3; i++) {
        float w = Wg[i * GATE_OUT + o];
#pragma unroll
        for (int rr = 0; rr < 16; rr++) acc[rr] = fmaf(in_s[rr][i], w, acc[rr]);
    }
    float bias = bg[o];
#pragma unroll
    for (int rr = 0; rr < 16; rr++) {
        int row = row0 + rr;
        int b = row >> 11, n = row & 2047;
        float v = 1.0f / (1.0f + expf(-(acc[rr] + bias)));
        if (o < 64) {
            float sv = st[row * 64 + o];
            g_C0[n * BC + b * C_IN + 2 + o] = v * sv;           // z * state
            if (o < 2) g_C0[n * BC + b * C_IN + o] = x[row * 2 + o];
        } else {
            g_r[row * 64 + (o - 64)] = v;                        // r gate
        }
    }
}

// ---------------- K5: update projection + tanh + GRU blend -----------------
__global__ void __launch_bounds__(128)
update_kernel(const float* __restrict__ st, const float* __restrict__ Wu,
              const float* __restrict__ bu, float* __restrict__ out) {
    __shared__ float in_s[16][IN3];
    int row0 = blockIdx.x * 16;
    int t = threadIdx.x;

    for (int idx = t; idx < 16 * IN3; idx += 128) {
        int rr = idx / IN3, i = idx - rr * IN3;
        int row = row0 + rr;
        int b = row >> 11, n = row & 2047;
        int k = i / C_IN, c = i - k * C_IN;
        const float* src = (k == 0) ? g_C0 : (k == 1) ? g_C1 : g_C2;
        in_s[rr][i] = src[n * BC + b * C_IN + c];
    }
    __syncthreads();

    int o = t & 63, hh = t >> 6;
    float acc[8];
#pragma unroll
    for (int rr = 0; rr < 8; rr++) acc[rr] = 0.0f;
    for (int i = 0; i < IN3; i++) {
        float w = Wu[i * UPD_OUT + o];
#pragma unroll
        for (int rr = 0; rr < 8; rr++) acc[rr] = fmaf(in_s[hh * 8 + rr][i], w, acc[rr]);
    }
    float bias = bu[o];
#pragma unroll
    for (int rr = 0; rr < 8; rr++) {
        int row = row0 + hh * 8 + rr;
        float hc = tanhf(acc[rr] + bias);
        float rv = g_r[row * 64 + o];
        float sv = st[row * 64 + o];
        out[row * 64 + o] = rv * sv + (1.0f - rv) * hc;
    }
}

// ---------------- launch ----------------------------------------------------
extern "C" void kernel_launch(void* const* d_in, const int* in_sizes, int n_in,
                              void* d_out, int out_size) {
    const float* x  = (const float*)d_in[0];
    const float* st = (const float*)d_in[1];
    const float* E  = (const float*)d_in[2];
    const float* Wg = (const float*)d_in[3];
    const float* bg = (const float*)d_in[4];
    const float* Wu = (const float*)d_in[5];
    const float* bu = (const float*)d_in[6];
    float* out = (float*)d_out;

    __nv_bfloat16 *pAhi, *pAlo, *pX0Thi, *pX0Tlo, *pX1Thi, *pX1Tlo;
    __nv_bfloat16 *pC0Thi, *pC0Tlo, *pC1Thi, *pC1Tlo;
    float *pX0, *pX1, *pX2, *pC0, *pC1, *pC2;
    cudaGetSymbolAddress((void**)&pAhi,   g_Ahi);
    cudaGetSymbolAddress((void**)&pAlo,   g_Alo);
    cudaGetSymbolAddress((void**)&pX0Thi, g_X0Thi);
    cudaGetSymbolAddress((void**)&pX0Tlo, g_X0Tlo);
    cudaGetSymbolAddress((void**)&pX1Thi, g_X1Thi);
    cudaGetSymbolAddress((void**)&pX1Tlo, g_X1Tlo);
    cudaGetSymbolAddress((void**)&pC0Thi, g_C0Thi);
    cudaGetSymbolAddress((void**)&pC0Tlo, g_C0Tlo);
    cudaGetSymbolAddress((void**)&pC1Thi, g_C1Thi);
    cudaGetSymbolAddress((void**)&pC1Tlo, g_C1Tlo);
    cudaGetSymbolAddress((void**)&pX0, g_X0);
    cudaGetSymbolAddress((void**)&pX1, g_X1);
    cudaGetSymbolAddress((void**)&pX2, g_X2);
    cudaGetSymbolAddress((void**)&pC0, g_C0);
    cudaGetSymbolAddress((void**)&pC1, g_C1);
    cudaGetSymbolAddress((void**)&pC2, g_C2);

    const int SMEM_BYTES = 2 * 73728;   // 147456 (epilogue Ct uses 135168)
    cudaFuncSetAttribute(mma_gemm<0>, cudaFuncAttributeMaxDynamicSharedMemorySize, SMEM_BYTES);
    cudaFuncSetAttribute(mma_gemm<1>, cudaFuncAttributeMaxDynamicSharedMemorySize, SMEM_BYTES);

    dim3 gg(NPAD / 128, N_NODES / 256);   // (17, 8) = 136 CTAs, single wave
    dim3 tg(NPAD / 64, N_NODES / 64);     // (34, 32) transpose tiles

    supports_kernel<<<N_NODES, 256>>>(E);
    pack_kernel<<<N_NODES, 256>>>(x, st);
    transpose_split_kernel<<<tg, 256>>>(pX0, pX0Thi, pX0Tlo);

    // gate gconv: X1 = A X0 ; X2 = 2 A X1 - X0
    mma_gemm<0><<<gg, 256, SMEM_BYTES>>>(pAhi, pAlo, pX0Thi, pX0Tlo,
                                         pX1, pX1Thi, pX1Tlo, nullptr);
    mma_gemm<1><<<gg, 256, SMEM_BYTES>>>(pAhi, pAlo, pX1Thi, pX1Tlo,
                                         pX2, nullptr, nullptr, pX0);

    gate_kernel<<<(BATCH * N_NODES) / 16, 128>>>(x, st, Wg, bg);
    transpose_split_kernel<<<tg, 256>>>(pC0, pC0Thi, pC0Tlo);

    // update gconv: C1 = A C0 ; C2 = 2 A C1 - C0
    mma_gemm<0><<<gg, 256, SMEM_BYTES>>>(pAhi, pAlo, pC0Thi, pC0Tlo,
                                         pC1, pC1Thi, pC1Tlo, nullptr);
    mma_gemm<1><<<gg, 256, SMEM_BYTES>>>(pAhi, pAlo, pC1Thi, pC1Tlo,
                                         pC2, nullptr, nullptr, pC0);

    update_kernel<<<(BATCH * N_NODES) / 16, 128>>>(st, Wu, bu, out);
}

// round 10
// speedup vs baseline: 1.5067x; 1.2888x over previous
#include <cuda_runtime.h>
#include <cuda_fp16.h>
#include <math.h>
#include <stdint.h>

#define N_NODES 2048
#define BATCH   32
#define HIDDEN  64
#define C_IN    66                 // DIM_IN + HIDDEN
#define BC      2112               // BATCH * C_IN
#define NPAD    2176               // BC padded to multiple of 128
#define IN3     198                // 3 * C_IN
#define GATE_OUT 128
#define UPD_OUT  64

// ---------------- device scratch (static: no allocations allowed) ----------
__device__ __half g_Ah  [N_NODES * N_NODES];
__device__ __half g_X0Thi[NPAD * N_NODES];
__device__ __half g_X0Tlo[NPAD * N_NODES];
__device__ __half g_X1Thi[NPAD * N_NODES];
__device__ __half g_X1Tlo[NPAD * N_NODES];
__device__ __half g_C0Thi[NPAD * N_NODES];
__device__ __half g_C0Tlo[NPAD * N_NODES];
__device__ __half g_C1Thi[NPAD * N_NODES];
__device__ __half g_C1Tlo[NPAD * N_NODES];
__device__ float g_X0[N_NODES * BC];
__device__ float g_X1[N_NODES * BC];
__device__ float g_X2[N_NODES * BC];
__device__ float g_C0[N_NODES * BC];
__device__ float g_C1[N_NODES * BC];
__device__ float g_C2[N_NODES * BC];
__device__ float g_r [BATCH * N_NODES * HIDDEN];

__device__ __forceinline__ uint32_t smem_to_u32(const void* p) {
    uint32_t a;
    asm("{ .reg .u64 t; cvta.to.shared.u64 t, %1; cvt.u32.u64 %0, t; }" : "=r"(a) : "l"(p));
    return a;
}
__device__ __forceinline__ void split_fp16(float v, __half& hi, __half& lo) {
    hi = __float2half_rn(v);
    lo = __float2half_rn(v - __half2float(hi));
}
__device__ __forceinline__ void mma_fp16(float* c, const uint32_t* a, const uint32_t* b) {
    asm volatile(
        "mma.sync.aligned.m16n8k16.row.col.f32.f16.f16.f32 "
        "{%0,%1,%2,%3}, {%4,%5,%6,%7}, {%8,%9}, {%0,%1,%2,%3};"
        : "+f"(c[0]), "+f"(c[1]), "+f"(c[2]), "+f"(c[3])
        : "r"(a[0]), "r"(a[1]), "r"(a[2]), "r"(a[3]), "r"(b[0]), "r"(b[1]));
}
__device__ __forceinline__ void ldsm4(uint32_t* r, uint32_t addr) {
    asm volatile("ldmatrix.sync.aligned.m8n8.x4.shared.b16 {%0,%1,%2,%3}, [%4];"
                 : "=r"(r[0]), "=r"(r[1]), "=r"(r[2]), "=r"(r[3]) : "r"(addr));
}
__device__ __forceinline__ void cp16(uint32_t daddr, const void* g) {
    asm volatile("cp.async.cg.shared.global [%0], [%1], 16;" :: "r"(daddr), "l"(g));
}

// ---------------- K1: supports = softmax(relu(E E^T)) -> fp16 --------------
__global__ void supports_kernel(const float* __restrict__ E) {
    int n = blockIdx.x;
    int t = threadIdx.x;                      // 256 threads, 8 cols each
    float e[10];
#pragma unroll
    for (int c = 0; c < 10; c++) e[c] = E[n * 10 + c];

    float vals[8];
    float vmax = 0.0f;
#pragma unroll
    for (int j = 0; j < 8; j++) {
        int m = j * 256 + t;
        float s = 0.0f;
#pragma unroll
        for (int c = 0; c < 10; c++) s = fmaf(e[c], E[m * 10 + c], s);
        s = fmaxf(s, 0.0f);
        vals[j] = s;
        vmax = fmaxf(vmax, s);
    }
    __shared__ float red[256];
    red[t] = vmax; __syncthreads();
    for (int s = 128; s > 0; s >>= 1) {
        if (t < s) red[t] = fmaxf(red[t], red[t + s]);
        __syncthreads();
    }
    vmax = red[0]; __syncthreads();

    float lsum = 0.0f;
#pragma unroll
    for (int j = 0; j < 8; j++) { vals[j] = expf(vals[j] - vmax); lsum += vals[j]; }
    red[t] = lsum; __syncthreads();
    for (int s = 128; s > 0; s >>= 1) {
        if (t < s) red[t] += red[t + s];
        __syncthreads();
    }
    float inv = 1.0f / red[0];
#pragma unroll
    for (int j = 0; j < 8; j++)
        g_Ah[(size_t)n * N_NODES + j * 256 + t] = __float2half_rn(vals[j] * inv);
}

// ---------------- K2: pack X0 fp32 [node][bc] only (coalesced) -------------
__global__ void pack_kernel(const float* __restrict__ x, const float* __restrict__ st) {
    int n = blockIdx.x;
    for (int i = threadIdx.x; i < BC; i += blockDim.x) {
        int b = i / C_IN, c = i - b * C_IN;
        float v = (c < 2) ? x[(b * N_NODES + n) * 2 + c]
                          : st[(b * N_NODES + n) * 64 + (c - 2)];
        g_X0[n * BC + i] = v;
    }
}

// ---------------- K3: tiled transpose+split: src[N][BC] -> dst[NPAD][N] ----
__global__ void __launch_bounds__(256)
transpose_split_kernel(const float* __restrict__ src,
                       __half* __restrict__ dhi,
                       __half* __restrict__ dlo) {
    __shared__ float tile[64][65];
    int i0 = blockIdx.x * 64;          // col in src = row in dst
    int n0 = blockIdx.y * 64;
    int t = threadIdx.x;
    int iloc = t >> 2;                 // 0..63
    int seg  = (t & 3) * 16;           // 16 elems per thread

    if (i0 < BC) {
        int nloc = t >> 2;
#pragma unroll
        for (int g = 0; g < 4; g++) {
            float4 v = *(const float4*)(src + (size_t)(n0 + nloc) * BC + i0 + seg + g * 4);
            tile[seg + g * 4 + 0][nloc] = v.x;
            tile[seg + g * 4 + 1][nloc] = v.y;
            tile[seg + g * 4 + 2][nloc] = v.z;
            tile[seg + g * 4 + 3][nloc] = v.w;
        }
        __syncthreads();
        __half hi[16], lo[16];
#pragma unroll
        for (int g = 0; g < 16; g++)
            split_fp16(tile[iloc][seg + g], hi[g], lo[g]);
        size_t off = (size_t)(i0 + iloc) * N_NODES + n0 + seg;
        *(uint4*)(dhi + off)     = *(uint4*)&hi[0];
        *(uint4*)(dhi + off + 8) = *(uint4*)&hi[8];
        *(uint4*)(dlo + off)     = *(uint4*)&lo[0];
        *(uint4*)(dlo + off + 8) = *(uint4*)&lo[8];
    } else {                            // pad rows: zeros
        uint4 z = make_uint4(0, 0, 0, 0);
        size_t off = (size_t)(i0 + iloc) * N_NODES + n0 + seg;
        *(uint4*)(dhi + off)     = z;
        *(uint4*)(dhi + off + 8) = z;
        *(uint4*)(dlo + off)     = z;
        *(uint4*)(dlo + off + 8) = z;
    }
}

// ---------------- HMMA GEMM: D[m,n] = sum_k A[m,k] * BT[n,k] ---------------
// fp16 2-split (A*Bhi + A*Blo), fp32 acc.
// CTA tile 256x128, 8 warps of 64x64, BK=32, cp.async double buffer.
// smem per buffer (49152B): A@0 (2 slices x 12288), Bhi@24576 (2 x 6144),
//                           Blo@36864. Row stride 48B -> conflict-free ldsm.
template <int MODE>
__global__ void __launch_bounds__(256, 1)
mma_gemm(const __half* __restrict__ Ah,
         const __half* __restrict__ Bhi, const __half* __restrict__ Blo,
         float* __restrict__ Cf, __half* __restrict__ CThi,
         __half* __restrict__ CTlo, const float* __restrict__ Aux) {
    extern __shared__ char smem[];
    const uint32_t sb = smem_to_u32(smem);
    const int tid = threadIdx.x, wid = tid >> 5, lane = tid & 31;
    const int wr = wid >> 1, wc = wid & 1;            // warp tile: 64x64
    const int m0 = blockIdx.y * 256, n0 = blockIdx.x * 128;

    const __half* srcA = Ah + (size_t)m0 * N_NODES;
    const __half* srcB[2] = { Bhi + (size_t)n0 * N_NODES,
                              Blo + (size_t)n0 * N_NODES };

    float acc[4][8][4];
#pragma unroll
    for (int i = 0; i < 4; i++)
#pragma unroll
        for (int j = 0; j < 8; j++)
#pragma unroll
            for (int k = 0; k < 4; k++) acc[i][j][k] = 0.f;

#define COPY_CHUNK(k0, bufi) do {                                             \
        uint32_t _b = sb + (bufi) * 49152;                                    \
        _Pragma("unroll")                                                     \
        for (int _u = 0; _u < 4; _u++) {          /* A: 4 units */            \
            int _unit = _u * 256 + tid;                                       \
            int _row = _unit >> 2, _q = _unit & 3;                            \
            int _sl = _q >> 1, _hf = _q & 1;                                  \
            cp16(_b + _sl * 12288 + _row * 48 + _hf * 16,                     \
                 srcA + (size_t)_row * N_NODES + (k0) + _sl * 16 + _hf * 8);  \
        }                                                                     \
        _Pragma("unroll")                                                     \
        for (int _t = 0; _t < 2; _t++) {          /* B hi/lo: 2 units */      \
            _Pragma("unroll")                                                 \
            for (int _u = 0; _u < 2; _u++) {                                  \
                int _unit = _u * 256 + tid;                                   \
                int _row = _unit >> 2, _q = _unit & 3;                        \
                int _sl = _q >> 1, _hf = _q & 1;                              \
                cp16(_b + 24576 + _t * 12288 + _sl * 6144 + _row * 48 + _hf * 16, \
                     srcB[_t] + (size_t)_row * N_NODES + (k0) + _sl * 16 + _hf * 8); \
            }                                                                 \
        }                                                                     \
        asm volatile("cp.async.commit_group;");                               \
    } while (0)

    COPY_CHUNK(0, 0);

    const int NCHUNK = N_NODES / 32;   // 64
    for (int c = 0; c < NCHUNK; c++) {
        int buf = c & 1;
        if (c + 1 < NCHUNK) {
            COPY_CHUNK((c + 1) * 32, buf ^ 1);
            asm volatile("cp.async.wait_group 1;");
        } else {
            asm volatile("cp.async.wait_group 0;");
        }
        __syncthreads();

        uint32_t base = sb + buf * 49152;

#pragma unroll
        for (int s = 0; s < 2; s++) {
            uint32_t a_f[4][4], b_hi[4][4], b_lo[4][4];
            int a_roff = (wr * 64 + (lane & 15)) * 48 + (lane >> 4) * 16 + s * 12288;
#pragma unroll
            for (int mt = 0; mt < 4; mt++)
                ldsm4(a_f[mt], base + a_roff + mt * 768);
            int q = lane >> 3, rl = lane & 7;
            int b_roff = (wc * 64 + (q >> 1) * 8 + rl) * 48 + (q & 1) * 16 + s * 6144;
#pragma unroll
            for (int p = 0; p < 4; p++) {
                ldsm4(b_hi[p], base + 24576 + b_roff + p * 768);
                ldsm4(b_lo[p], base + 36864 + b_roff + p * 768);
            }
#pragma unroll
            for (int mt = 0; mt < 4; mt++) {
#pragma unroll
                for (int nt = 0; nt < 8; nt++) {
                    const uint32_t* bh = &b_hi[nt >> 1][(nt & 1) * 2];
                    const uint32_t* bl = &b_lo[nt >> 1][(nt & 1) * 2];
                    mma_fp16(acc[mt][nt], a_f[mt], bh);
                    mma_fp16(acc[mt][nt], a_f[mt], bl);
                }
            }
        }
        __syncthreads();
    }
#undef COPY_CHUNK

    // ---- epilogue: fp32 row-major direct from fragments ----
    const int frow = lane >> 2, fcol = (lane & 3) * 2;
#pragma unroll
    for (int mt = 0; mt < 4; mt++) {
#pragma unroll
        for (int nt = 0; nt < 8; nt++) {
            int m = m0 + wr * 64 + mt * 16 + frow;
            int n = n0 + wc * 64 + nt * 8 + fcol;
            if (n < BC) {
                float* d0 = Cf + (size_t)m * BC + n;
                float* d1 = Cf + (size_t)(m + 8) * BC + n;
                if (MODE == 1) {
                    float2 x0 = *(const float2*)(Aux + (size_t)m * BC + n);
                    float2 x1 = *(const float2*)(Aux + (size_t)(m + 8) * BC + n);
                    *(float2*)d0 = make_float2(2.f * acc[mt][nt][0] - x0.x,
                                               2.f * acc[mt][nt][1] - x0.y);
                    *(float2*)d1 = make_float2(2.f * acc[mt][nt][2] - x1.x,
                                               2.f * acc[mt][nt][3] - x1.y);
                } else {
                    *(float2*)d0 = make_float2(acc[mt][nt][0], acc[mt][nt][1]);
                    *(float2*)d1 = make_float2(acc[mt][nt][2], acc[mt][nt][3]);
                }
            }
        }
    }

    if (MODE == 0) {
        // ---- transpose via smem -> fp16 hi/lo [n][node] ----
        float* Ct = (float*)smem;          // [128][264] fp32 = 135168B
        __syncthreads();
#pragma unroll
        for (int mt = 0; mt < 4; mt++) {
#pragma unroll
            for (int nt = 0; nt < 8; nt++) {
                int mloc = wr * 64 + mt * 16 + frow;
                int nloc = wc * 64 + nt * 8 + fcol;
                Ct[(nloc + 0) * 264 + mloc]     = acc[mt][nt][0];
                Ct[(nloc + 1) * 264 + mloc]     = acc[mt][nt][1];
                Ct[(nloc + 0) * 264 + mloc + 8] = acc[mt][nt][2];
                Ct[(nloc + 1) * 264 + mloc + 8] = acc[mt][nt][3];
            }
        }
        __syncthreads();
        for (int it = 0; it < 16; it++) {
            int nloc = it * 8 + wid;
#pragma unroll
            for (int j = 0; j < 2; j++) {
                int mloc = lane * 4 + j * 128;
                float4 v = *(float4*)&Ct[nloc * 264 + mloc];
                __half hi[4], lo[4];
                split_fp16(v.x, hi[0], lo[0]);
                split_fp16(v.y, hi[1], lo[1]);
                split_fp16(v.z, hi[2], lo[2]);
                split_fp16(v.w, hi[3], lo[3]);
                size_t off = (size_t)(n0 + nloc) * N_NODES + m0 + mloc;
                *(uint2*)(CThi + off) = *(uint2*)hi;
                *(uint2*)(CTlo + off) = *(uint2*)lo;
            }
        }
    }
}

// ---------------- K4: gate projection + sigmoid + candidate pack -----------
__global__ void __launch_bounds__(128)
gate_kernel(const float* __restrict__ x, const float* __restrict__ st,
            const float* __restrict__ Wg, const float* __restrict__ bg) {
    __shared__ float in_s[16][IN3];
    int row0 = blockIdx.x * 16;
    int t = threadIdx.x;

    for (int idx = t; idx < 16 * IN3; idx += 128) {
        int rr = idx / IN3, i = idx - rr * IN3;
        int row = row0 + rr;
        int b = row >> 11, n = row & 2047;
        int k = i / C_IN, c = i - k * C_IN;
        const float* src = (k == 0) ? g_X0 : (k == 1) ? g_X1 : g_X2;
        in_s[rr][i] = src[n * BC + b * C_IN + c];
    }
    __syncthreads();

    int o = t;
    float acc[16];
#pragma unroll
    for (int rr = 0; rr < 16; rr++) acc[rr] = 0.0f;
    for (int i = 0; i < IN3; i++) {
        float w = Wg[i * GATE_OUT + o];
#pragma unroll
        for (int rr = 0; rr < 16; rr++) acc[rr] = fmaf(in_s[rr][i], w, acc[rr]);
    }
    float bias = bg[o];
#pragma unroll
    for (int rr = 0; rr < 16; rr++) {
        int row = row0 + rr;
        int b = row >> 11, n = row & 2047;
        float v = 1.0f / (1.0f + expf(-(acc[rr] + bias)));
        if (o < 64) {
            float sv = st[row * 64 + o];
            g_C0[n * BC + b * C_IN + 2 + o] = v * sv;           // z * state
            if (o < 2) g_C0[n * BC + b * C_IN + o] = x[row * 2 + o];
        } else {
            g_r[row * 64 + (o - 64)] = v;                        // r gate
        }
    }
}

// ---------------- K5: update projection + tanh + GRU blend -----------------
__global__ void __launch_bounds__(128)
update_kernel(const float* __restrict__ st, const float* __restrict__ Wu,
              const float* __restrict__ bu, float* __restrict__ out) {
    __shared__ float in_s[16][IN3];
    int row0 = blockIdx.x * 16;
    int t = threadIdx.x;

    for (int idx = t; idx < 16 * IN3; idx += 128) {
        int rr = idx / IN3, i = idx - rr * IN3;
        int row = row0 + rr;
        int b = row >> 11, n = row & 2047;
        int k = i / C_IN, c = i - k * C_IN;
        const float* src = (k == 0) ? g_C0 : (k == 1) ? g_C1 : g_C2;
        in_s[rr][i] = src[n * BC + b * C_IN + c];
    }
    __syncthreads();

    int o = t & 63, hh = t >> 6;
    float acc[8];
#pragma unroll
    for (int rr = 0; rr < 8; rr++) acc[rr] = 0.0f;
    for (int i = 0; i < IN3; i++) {
        float w = Wu[i * UPD_OUT + o];
#pragma unroll
        for (int rr = 0; rr < 8; rr++) acc[rr] = fmaf(in_s[hh * 8 + rr][i], w, acc[rr]);
    }
    float bias = bu[o];
#pragma unroll
    for (int rr = 0; rr < 8; rr++) {
        int row = row0 + hh * 8 + rr;
        float hc = tanhf(acc[rr] + bias);
        float rv = g_r[row * 64 + o];
        float sv = st[row * 64 + o];
        out[row * 64 + o] = rv * sv + (1.0f - rv) * hc;
    }
}

// ---------------- launch ----------------------------------------------------
extern "C" void kernel_launch(void* const* d_in, const int* in_sizes, int n_in,
                              void* d_out, int out_size) {
    const float* x  = (const float*)d_in[0];
    const float* st = (const float*)d_in[1];
    const float* E  = (const float*)d_in[2];
    const float* Wg = (const float*)d_in[3];
    const float* bg = (const float*)d_in[4];
    const float* Wu = (const float*)d_in[5];
    const float* bu = (const float*)d_in[6];
    float* out = (float*)d_out;

    __half *pAh, *pX0Thi, *pX0Tlo, *pX1Thi, *pX1Tlo;
    __half *pC0Thi, *pC0Tlo, *pC1Thi, *pC1Tlo;
    float *pX0, *pX1, *pX2, *pC0, *pC1, *pC2;
    cudaGetSymbolAddress((void**)&pAh,    g_Ah);
    cudaGetSymbolAddress((void**)&pX0Thi, g_X0Thi);
    cudaGetSymbolAddress((void**)&pX0Tlo, g_X0Tlo);
    cudaGetSymbolAddress((void**)&pX1Thi, g_X1Thi);
    cudaGetSymbolAddress((void**)&pX1Tlo, g_X1Tlo);
    cudaGetSymbolAddress((void**)&pC0Thi, g_C0Thi);
    cudaGetSymbolAddress((void**)&pC0Tlo, g_C0Tlo);
    cudaGetSymbolAddress((void**)&pC1Thi, g_C1Thi);
    cudaGetSymbolAddress((void**)&pC1Tlo, g_C1Tlo);
    cudaGetSymbolAddress((void**)&pX0, g_X0);
    cudaGetSymbolAddress((void**)&pX1, g_X1);
    cudaGetSymbolAddress((void**)&pX2, g_X2);
    cudaGetSymbolAddress((void**)&pC0, g_C0);
    cudaGetSymbolAddress((void**)&pC1, g_C1);
    cudaGetSymbolAddress((void**)&pC2, g_C2);

    const int SMEM_BYTES = 135168;   // max(2*49152 mainloop, 135168 epilogue Ct)
    cudaFuncSetAttribute(mma_gemm<0>, cudaFuncAttributeMaxDynamicSharedMemorySize, SMEM_BYTES);
    cudaFuncSetAttribute(mma_gemm<1>, cudaFuncAttributeMaxDynamicSharedMemorySize, SMEM_BYTES);

    dim3 gg(NPAD / 128, N_NODES / 256);   // (17, 8) = 136 CTAs, single wave
    dim3 tg(NPAD / 64, N_NODES / 64);     // (34, 32) transpose tiles

    supports_kernel<<<N_NODES, 256>>>(E);
    pack_kernel<<<N_NODES, 256>>>(x, st);
    transpose_split_kernel<<<tg, 256>>>(pX0, pX0Thi, pX0Tlo);

    // gate gconv: X1 = A X0 ; X2 = 2 A X1 - X0
    mma_gemm<0><<<gg, 256, SMEM_BYTES>>>(pAh, pX0Thi, pX0Tlo,
                                         pX1, pX1Thi, pX1Tlo, nullptr);
    mma_gemm<1><<<gg, 256, SMEM_BYTES>>>(pAh, pX1Thi, pX1Tlo,
                                         pX2, nullptr, nullptr, pX0);

    gate_kernel<<<(BATCH * N_NODES) / 16, 128>>>(x, st, Wg, bg);
    transpose_split_kernel<<<tg, 256>>>(pC0, pC0Thi, pC0Tlo);

    // update gconv: C1 = A C0 ; C2 = 2 A C1 - C0
    mma_gemm<0><<<gg, 256, SMEM_BYTES>>>(pAh, pC0Thi, pC0Tlo,
                                         pC1, pC1Thi, pC1Tlo, nullptr);
    mma_gemm<1><<<gg, 256, SMEM_BYTES>>>(pAh, pC1Thi, pC1Tlo,
                                         pC2, nullptr, nullptr, pC0);

    update_kernel<<<(BATCH * N_NODES) / 16, 128>>>(st, Wu, bu, out);
}